// round 5
// baseline (speedup 1.0000x reference)
#include <cuda_runtime.h>
#include <cuda_bf16.h>
#include <cstdint>

// ---------------- problem dims ----------------
#define PP 2
#define JJ 32
#define KK 32
#define MM 128
#define LL 16
#define NN 128
#define BATCH 512
#define KN 4096
#define JM 4096
#define BKC 64                 // GEMM K-chunk (bf16 elements)
#define NCHUNK (KN / BKC)      // 64
#define STAGE 49152            // bytes per pipeline stage (A + Bhi + Blo, 16KB each)

// ---------------- device scratch (no cudaMalloc allowed) ----------------
__device__ float g_pmax[256];
__device__ float g_pmin[256];
__device__ float g_scale;
__device__ __nv_bfloat16 g_q[(size_t)BATCH * KN];         // quantized activations (exact ints)
__device__ __nv_bfloat16 g_Whi[(size_t)JM * KN];          // bf16 high part of W
__device__ __nv_bfloat16 g_Wlo[(size_t)JM * KN];          // bf16 low  part of W

// ---------------- PTX helpers (sm_100-safe only) ----------------
__device__ __forceinline__ uint32_t smem_u32(const void* p) {
    uint32_t a;
    asm("{ .reg .u64 t; cvta.to.shared.u64 t, %1; cvt.u32.u64 %0, t; }" : "=r"(a) : "l"(p));
    return a;
}

__device__ __forceinline__ void cp16(uint32_t dst, const void* src) {
    asm volatile("cp.async.cg.shared.global [%0], [%1], 16;\n" :: "r"(dst), "l"(src));
}
#define CP_COMMIT() asm volatile("cp.async.commit_group;\n" ::: "memory")
#define CP_WAIT(n)  asm volatile("cp.async.wait_group %0;\n" :: "n"(n) : "memory")

__device__ __forceinline__ void ldsm4(uint32_t* r, uint32_t addr) {
    asm volatile("ldmatrix.sync.aligned.m8n8.x4.shared.b16 {%0,%1,%2,%3}, [%4];"
        : "=r"(r[0]), "=r"(r[1]), "=r"(r[2]), "=r"(r[3]) : "r"(addr));
}

__device__ __forceinline__ void mma16816(float* c, const uint32_t* a, const uint32_t* b) {
    asm volatile(
        "mma.sync.aligned.m16n8k16.row.col.f32.bf16.bf16.f32 "
        "{%0,%1,%2,%3}, {%4,%5,%6,%7}, {%8,%9}, {%0,%1,%2,%3};"
        : "+f"(c[0]), "+f"(c[1]), "+f"(c[2]), "+f"(c[3])
        : "r"(a[0]), "r"(a[1]), "r"(a[2]), "r"(a[3]), "r"(b[0]), "r"(b[1]));
}

// ---------------- kernel 1: per-block min/max partials ----------------
__global__ void __launch_bounds__(256) k_minmax(const float* __restrict__ x, int n4) {
    const float4* x4 = (const float4*)x;
    float mx = -3.4e38f, mn = 3.4e38f;
    for (int i = blockIdx.x * blockDim.x + threadIdx.x; i < n4; i += gridDim.x * blockDim.x) {
        float4 v = x4[i];
        mx = fmaxf(mx, fmaxf(fmaxf(v.x, v.y), fmaxf(v.z, v.w)));
        mn = fminf(mn, fminf(fminf(v.x, v.y), fminf(v.z, v.w)));
    }
    __shared__ float smx[256], smn[256];
    int t = threadIdx.x;
    smx[t] = mx; smn[t] = mn;
    __syncthreads();
    for (int s = 128; s > 0; s >>= 1) {
        if (t < s) { smx[t] = fmaxf(smx[t], smx[t + s]); smn[t] = fminf(smn[t], smn[t + s]); }
        __syncthreads();
    }
    if (t == 0) { g_pmax[blockIdx.x] = smx[0]; g_pmin[blockIdx.x] = smn[0]; }
}

// ---------------- kernel 2: finalize act_scale ----------------
__global__ void __launch_bounds__(256) k_scale() {
    __shared__ float smx[256], smn[256];
    int t = threadIdx.x;
    smx[t] = g_pmax[t]; smn[t] = g_pmin[t];
    __syncthreads();
    for (int s = 128; s > 0; s >>= 1) {
        if (t < s) { smx[t] = fmaxf(smx[t], smx[t + s]); smn[t] = fminf(smn[t], smn[t + s]); }
        __syncthreads();
    }
    if (t == 0) {
        float s = __fdiv_rn(smx[0] - smn[0], 254.0f);   // (max-min)/(2*qmax), qmax=127
        g_scale = fmaxf(s, 1e-8f);
    }
}

// ---------------- kernel 3: quantize activations to exact bf16 integers ----------------
__global__ void __launch_bounds__(256) k_quant(const float* __restrict__ x) {
    float s = g_scale;
    int i = blockIdx.x * blockDim.x + threadIdx.x;   // one float4 per thread
    const float4* x4 = (const float4*)x;
    float4 v = x4[i];
    float q0 = fminf(fmaxf(rintf(__fdiv_rn(v.x, s)), -127.f), 127.f);
    float q1 = fminf(fmaxf(rintf(__fdiv_rn(v.y, s)), -127.f), 127.f);
    float q2 = fminf(fmaxf(rintf(__fdiv_rn(v.z, s)), -127.f), 127.f);
    float q3 = fminf(fmaxf(rintf(__fdiv_rn(v.w, s)), -127.f), 127.f);
    union { __nv_bfloat16 h[4]; uint2 u; } pk;
    pk.h[0] = __float2bfloat16(q0);
    pk.h[1] = __float2bfloat16(q1);
    pk.h[2] = __float2bfloat16(q2);
    pk.h[3] = __float2bfloat16(q3);
    ((uint2*)g_q)[i] = pk.u;
}

// ---------------- kernel 4: build W tile per (j,k), split into bf16 hi/lo ----------------
__global__ void __launch_bounds__(256) k_buildw(const float* __restrict__ Ysign,
                                                const float* __restrict__ Zsign,
                                                const float* __restrict__ Yscale,
                                                const float* __restrict__ Zscale,
                                                const float* __restrict__ Aq) {
    __shared__ float sYs[2][MM * LL];   // [p][m*16+l]
    __shared__ float sZs[2][LL * NN];   // [p][l*128+n]
    __shared__ float sB[MM];
    __shared__ float sZr[NN];

    const int j = blockIdx.x >> 5;
    const int k = blockIdx.x & 31;
    const int tid = threadIdx.x;

    float ysc[2], zsc[2], a0[2], a1[2], a2[2];
    float a3s = 0.f;
#pragma unroll
    for (int p = 0; p < 2; p++) {
        int idx = (p * JJ + j) * KK + k;
        ysc[p] = Yscale[idx]; zsc[p] = Zscale[idx];
        a0[p] = Aq[idx * 4 + 0]; a1[p] = Aq[idx * 4 + 1];
        a2[p] = Aq[idx * 4 + 2]; a3s += Aq[idx * 4 + 3];
        size_t base = (size_t)idx * (MM * LL);   // == idx * (LL*NN) too (both 2048)
        const float4* ys4 = (const float4*)(Ysign + base);
        const float4* zs4 = (const float4*)(Zsign + base);
        float4* dY = (float4*)sYs[p];
        float4* dZ = (float4*)sZs[p];
        dY[tid] = ys4[tid]; dY[tid + 256] = ys4[tid + 256];
        dZ[tid] = zs4[tid]; dZ[tid + 256] = zs4[tid + 256];
    }
    __syncthreads();

    if (tid < 128) {
        int m = tid; float b = 0.f;
#pragma unroll
        for (int p = 0; p < 2; p++) {
            float s = 0.f;
#pragma unroll
            for (int l = 0; l < 16; l++) s += sYs[p][m * 16 + l];
            b += a1[p] * ysc[p] * s;
        }
        sB[m] = b;
    } else {
        int n = tid - 128; float z = 0.f;
#pragma unroll
        for (int p = 0; p < 2; p++) {
            float s = 0.f;
#pragma unroll
            for (int l = 0; l < 16; l++) s += sZs[p][l * 128 + n];
            z += a2[p] * zsc[p] * s;
        }
        sZr[n] = z;
    }
    __syncthreads();

    const int n = tid & 127;
    const int mh = tid >> 7;
    float zc0[16], zc1[16];
#pragma unroll
    for (int l = 0; l < 16; l++) { zc0[l] = sZs[0][l * 128 + n]; zc1[l] = sZs[1][l * 128 + n]; }
    const float c00 = a0[0] * ysc[0] * zsc[0];
    const float c01 = a0[1] * ysc[1] * zsc[1];
    const float addn = sZr[n] + a3s;
    const size_t colbase = (size_t)k * 128 + n;

    for (int mi = 0; mi < 64; mi++) {
        const int m = mh * 64 + mi;
        const float4* y0 = (const float4*)(sYs[0] + m * 16);
        const float4* y1 = (const float4*)(sYs[1] + m * 16);
        float d0 = 0.f, d1 = 0.f;
#pragma unroll
        for (int l4 = 0; l4 < 4; l4++) {
            float4 a = y0[l4];
            d0 += a.x * zc0[l4 * 4 + 0] + a.y * zc0[l4 * 4 + 1] + a.z * zc0[l4 * 4 + 2] + a.w * zc0[l4 * 4 + 3];
            float4 b = y1[l4];
            d1 += b.x * zc1[l4 * 4 + 0] + b.y * zc1[l4 * 4 + 1] + b.z * zc1[l4 * 4 + 2] + b.w * zc1[l4 * 4 + 3];
        }
        float w = c00 * d0 + c01 * d1 + sB[m] + addn;
        __nv_bfloat16 hi = __float2bfloat16(w);
        float r = w - __bfloat162float(hi);
        __nv_bfloat16 lo = __float2bfloat16(r);
        size_t off = (size_t)(j * 128 + m) * KN + colbase;
        g_Whi[off] = hi;
        g_Wlo[off] = lo;
    }
}

// ---------------- kernel 5: warp-MMA GEMM out = act*(q @ (Whi+Wlo)^T) + bias ----------------
// CTA: 256 threads = 8 warps (4 m x 2 n). CTA tile 128(b) x 128(jm), K-chunk 64.
// 3-stage cp.async pipeline. Stage layout: A @+0 (16KB), Bhi @+16KB, Blo @+32KB.
// smem rows are 128B, XOR-swizzled (col16B ^= (row&7)<<4) => conflict-free ldmatrix.
__global__ void __launch_bounds__(256, 1) k_gemm(const float* __restrict__ bias,
                                                 float* __restrict__ out) {
    extern __shared__ char smem[];
    const uint32_t sbase = smem_u32(smem);

    const int tid = threadIdx.x;
    const int lane = tid & 31;
    const int wid = tid >> 5;
    const int jt = blockIdx.x;        // jm tile, 0..31
    const int bt = blockIdx.y;        // b tile,  0..3
    const int warp_m = wid >> 1;      // 0..3 -> m base warp_m*32
    const int warp_n = wid & 1;       // 0..1 -> n base warp_n*64

    // ---- cp.async source/dest offsets: 4 x 16B chunks per tile per thread ----
    uint32_t swoff[4];
    const char* srcq[4];
    const char* srch[4];
    const char* srcl[4];
    {
        const char* gq  = (const char*)(g_q   + (size_t)(bt * 128) * KN);
        const char* ghi = (const char*)(g_Whi + (size_t)(jt * 128) * KN);
        const char* glo = (const char*)(g_Wlo + (size_t)(jt * 128) * KN);
#pragma unroll
        for (int i = 0; i < 4; i++) {
            int idx = tid + i * 256;            // 0..1023
            int row = idx >> 3;                 // 0..127
            int seg = (idx & 7) * 16;           // byte within 128B row
            swoff[i] = (uint32_t)(row * 128) + ((uint32_t)seg ^ (uint32_t)((row & 7) << 4));
            size_t gb = (size_t)row * (KN * 2) + seg;   // row stride 8192 B
            srcq[i] = gq + gb;
            srch[i] = ghi + gb;
            srcl[i] = glo + gb;
        }
    }

    // ---- prefetch chunks 0 and 1 ----
#pragma unroll
    for (int s = 0; s < 2; s++) {
        uint32_t base = sbase + s * STAGE;
        size_t koff = (size_t)s * 128;          // 64 bf16 = 128 bytes
#pragma unroll
        for (int i = 0; i < 4; i++) {
            cp16(base +         swoff[i], srcq[i] + koff);
            cp16(base + 16384 + swoff[i], srch[i] + koff);
            cp16(base + 32768 + swoff[i], srcl[i] + koff);
        }
        CP_COMMIT();
    }

    // ---- ldmatrix lane addressing ----
    const int a_row = warp_m * 32 + (lane & 15);           // + mt*16
    const uint32_t a_hi  = (uint32_t)((lane >> 4) * 16);
    const uint32_t a_swz = (uint32_t)((a_row & 7) << 4);   // invariant under +16
    const int b_g = lane >> 3;                              // 0..3
    const int b_row0 = warp_n * 64 + ((b_g >> 1) << 3) + (lane & 7);  // + i*16
    const uint32_t b_hi  = (uint32_t)((b_g & 1) * 16);
    const uint32_t b_swz = (uint32_t)((b_row0 & 7) << 4);  // invariant under +16

    float acc[2][8][4];
#pragma unroll
    for (int mt = 0; mt < 2; mt++)
#pragma unroll
        for (int nt = 0; nt < 8; nt++)
#pragma unroll
            for (int v = 0; v < 4; v++) acc[mt][nt][v] = 0.f;

    for (int c = 0; c < NCHUNK; c++) {
        // issue chunk c+2 into buf (c+2)%3 (freed by compute of chunk c-1)
        if (c + 2 < NCHUNK) {
            uint32_t base = sbase + ((c + 2) % 3) * STAGE;
            size_t koff = (size_t)(c + 2) * 128;
#pragma unroll
            for (int i = 0; i < 4; i++) {
                cp16(base +         swoff[i], srcq[i] + koff);
                cp16(base + 16384 + swoff[i], srch[i] + koff);
                cp16(base + 32768 + swoff[i], srcl[i] + koff);
            }
        }
        CP_COMMIT();            // commit (possibly empty) -> fixed group accounting
        CP_WAIT(2);             // chunk c complete
        __syncthreads();

        const uint32_t bb = sbase + (c % 3) * STAGE;
#pragma unroll
        for (int ks = 0; ks < 4; ks++) {
            uint32_t a[2][4];
#pragma unroll
            for (int mt = 0; mt < 2; mt++)
                ldsm4(a[mt], bb + (uint32_t)((a_row + mt * 16) * 128)
                              + (((uint32_t)(ks * 32) + a_hi) ^ a_swz));
            uint32_t bh[8][2], bl[8][2];
#pragma unroll
            for (int i = 0; i < 4; i++) {
                uint32_t ro = (uint32_t)((b_row0 + i * 16) * 128)
                            + (((uint32_t)(ks * 32) + b_hi) ^ b_swz);
                uint32_t r[4];
                ldsm4(r, bb + 16384 + ro);
                bh[2*i][0] = r[0]; bh[2*i][1] = r[1]; bh[2*i+1][0] = r[2]; bh[2*i+1][1] = r[3];
                ldsm4(r, bb + 32768 + ro);
                bl[2*i][0] = r[0]; bl[2*i][1] = r[1]; bl[2*i+1][0] = r[2]; bl[2*i+1][1] = r[3];
            }
#pragma unroll
            for (int mt = 0; mt < 2; mt++)
#pragma unroll
                for (int nt = 0; nt < 8; nt++) {
                    mma16816(acc[mt][nt], a[mt], bh[nt]);
                    mma16816(acc[mt][nt], a[mt], bl[nt]);
                }
        }
        __syncthreads();
    }

    // ---- epilogue: out = acc*act + bias ----
    const float act = g_scale;
    const int orow0 = bt * 128 + warp_m * 32 + (lane >> 2);
    const int ocol0 = jt * 128 + warp_n * 64 + (lane & 3) * 2;
#pragma unroll
    for (int mt = 0; mt < 2; mt++) {
        const int r0 = orow0 + mt * 16;
#pragma unroll
        for (int nt = 0; nt < 8; nt++) {
            const int col = ocol0 + nt * 8;
            const float2 b2 = *(const float2*)(bias + col);
            float2 v0, v1;
            v0.x = acc[mt][nt][0] * act + b2.x;
            v0.y = acc[mt][nt][1] * act + b2.y;
            v1.x = acc[mt][nt][2] * act + b2.x;
            v1.y = acc[mt][nt][3] * act + b2.y;
            *(float2*)(out + (size_t)r0 * JM + col)       = v0;
            *(float2*)(out + (size_t)(r0 + 8) * JM + col) = v1;
        }
    }
}

// ---------------- launcher ----------------
extern "C" void kernel_launch(void* const* d_in, const int* in_sizes, int n_in,
                              void* d_out, int out_size) {
    const float *x = nullptr, *Ys = nullptr, *Zs = nullptr;
    const float *Ysc = nullptr, *Zsc = nullptr, *A = nullptr, *bias = nullptr;
    for (int i = 0; i < n_in; i++) {
        const int s = in_sizes[i];
        const float* p = (const float*)d_in[i];
        if (s == BATCH * KN && !x) x = p;                                        // 2097152
        else if (s == PP * JJ * KK * MM * LL) { if (!Ys) Ys = p; else Zs = p; }  // 4194304 x2
        else if (s == PP * JJ * KK) { if (!Ysc) Ysc = p; else Zsc = p; }         // 2048 x2
        else if (s == PP * JJ * KK * 4) A = p;                                   // 8192
        else if (s == JM) bias = p;                                              // 4096
    }
    float* out = (float*)d_out;

    k_minmax<<<256, 256>>>(x, (BATCH * KN) / 4);
    k_scale<<<1, 256>>>();
    k_quant<<<(BATCH * KN) / 4 / 256, 256>>>(x);
    k_buildw<<<JJ * KK, 256>>>(Ys, Zs, Ysc, Zsc, A);

    const int smem_bytes = 3 * STAGE;   // 147456
    cudaFuncSetAttribute(k_gemm, cudaFuncAttributeMaxDynamicSharedMemorySize, smem_bytes);
    dim3 grid(JM / 128, BATCH / 128);
    k_gemm<<<grid, 256, smem_bytes>>>(bias, out);
}

// round 6
// speedup vs baseline: 1.1739x; 1.1739x over previous
#include <cuda_runtime.h>
#include <cuda_bf16.h>
#include <cstdint>

// ---------------- problem dims ----------------
#define PP 2
#define JJ 32
#define KK 32
#define MM 128
#define LL 16
#define NN 128
#define BATCH 512
#define KN 4096
#define JM 4096
#define BKC 64                 // GEMM K-chunk (bf16 elements)
#define NCHUNK (KN / BKC)      // 64
#define STAGE 49152            // bytes per pipeline stage (A + Bhi + Blo, 16KB each)

// ---------------- device scratch (no cudaMalloc allowed) ----------------
__device__ float g_pmax[256];
__device__ float g_pmin[256];
__device__ float g_scale;
__device__ __nv_bfloat16 g_q[(size_t)BATCH * KN];         // quantized activations (exact ints)
__device__ __nv_bfloat16 g_Whi[(size_t)JM * KN];          // bf16 high part of W
__device__ __nv_bfloat16 g_Wlo[(size_t)JM * KN];          // bf16 low  part of W

// ---------------- PTX helpers (sm_100-safe only) ----------------
__device__ __forceinline__ uint32_t smem_u32(const void* p) {
    uint32_t a;
    asm("{ .reg .u64 t; cvta.to.shared.u64 t, %1; cvt.u32.u64 %0, t; }" : "=r"(a) : "l"(p));
    return a;
}

__device__ __forceinline__ void cp16(uint32_t dst, const void* src) {
    asm volatile("cp.async.cg.shared.global [%0], [%1], 16;\n" :: "r"(dst), "l"(src));
}
#define CP_COMMIT() asm volatile("cp.async.commit_group;\n" ::: "memory")
#define CP_WAIT(n)  asm volatile("cp.async.wait_group %0;\n" :: "n"(n) : "memory")

__device__ __forceinline__ void ldsm4(uint32_t* r, uint32_t addr) {
    asm volatile("ldmatrix.sync.aligned.m8n8.x4.shared.b16 {%0,%1,%2,%3}, [%4];"
        : "=r"(r[0]), "=r"(r[1]), "=r"(r[2]), "=r"(r[3]) : "r"(addr));
}
__device__ __forceinline__ void ldsm4t(uint32_t* r, uint32_t addr) {
    asm volatile("ldmatrix.sync.aligned.m8n8.x4.trans.shared.b16 {%0,%1,%2,%3}, [%4];"
        : "=r"(r[0]), "=r"(r[1]), "=r"(r[2]), "=r"(r[3]) : "r"(addr));
}

__device__ __forceinline__ void mma16816(float* c, const uint32_t* a, const uint32_t* b) {
    asm volatile(
        "mma.sync.aligned.m16n8k16.row.col.f32.bf16.bf16.f32 "
        "{%0,%1,%2,%3}, {%4,%5,%6,%7}, {%8,%9}, {%0,%1,%2,%3};"
        : "+f"(c[0]), "+f"(c[1]), "+f"(c[2]), "+f"(c[3])
        : "r"(a[0]), "r"(a[1]), "r"(a[2]), "r"(a[3]), "r"(b[0]), "r"(b[1]));
}

// ---------------- kernel 1: per-block min/max partials ----------------
__global__ void __launch_bounds__(256) k_minmax(const float* __restrict__ x, int n4) {
    const float4* x4 = (const float4*)x;
    float mx = -3.4e38f, mn = 3.4e38f;
    for (int i = blockIdx.x * blockDim.x + threadIdx.x; i < n4; i += gridDim.x * blockDim.x) {
        float4 v = x4[i];
        mx = fmaxf(mx, fmaxf(fmaxf(v.x, v.y), fmaxf(v.z, v.w)));
        mn = fminf(mn, fminf(fminf(v.x, v.y), fminf(v.z, v.w)));
    }
    __shared__ float smx[256], smn[256];
    int t = threadIdx.x;
    smx[t] = mx; smn[t] = mn;
    __syncthreads();
    for (int s = 128; s > 0; s >>= 1) {
        if (t < s) { smx[t] = fmaxf(smx[t], smx[t + s]); smn[t] = fminf(smn[t], smn[t + s]); }
        __syncthreads();
    }
    if (t == 0) { g_pmax[blockIdx.x] = smx[0]; g_pmin[blockIdx.x] = smn[0]; }
}

// ---------------- kernel 2: finalize act_scale ----------------
__global__ void __launch_bounds__(256) k_scale() {
    __shared__ float smx[256], smn[256];
    int t = threadIdx.x;
    smx[t] = g_pmax[t]; smn[t] = g_pmin[t];
    __syncthreads();
    for (int s = 128; s > 0; s >>= 1) {
        if (t < s) { smx[t] = fmaxf(smx[t], smx[t + s]); smn[t] = fminf(smn[t], smn[t + s]); }
        __syncthreads();
    }
    if (t == 0) {
        float s = __fdiv_rn(smx[0] - smn[0], 254.0f);   // (max-min)/(2*qmax), qmax=127
        g_scale = fmaxf(s, 1e-8f);
    }
}

// ---------------- kernel 3: quantize activations to exact bf16 integers ----------------
__global__ void __launch_bounds__(256) k_quant(const float* __restrict__ x) {
    float s = g_scale;
    int i = blockIdx.x * blockDim.x + threadIdx.x;   // one float4 per thread
    const float4* x4 = (const float4*)x;
    float4 v = x4[i];
    float q0 = fminf(fmaxf(rintf(__fdiv_rn(v.x, s)), -127.f), 127.f);
    float q1 = fminf(fmaxf(rintf(__fdiv_rn(v.y, s)), -127.f), 127.f);
    float q2 = fminf(fmaxf(rintf(__fdiv_rn(v.z, s)), -127.f), 127.f);
    float q3 = fminf(fmaxf(rintf(__fdiv_rn(v.w, s)), -127.f), 127.f);
    union { __nv_bfloat16 h[4]; uint2 u; } pk;
    pk.h[0] = __float2bfloat16(q0);
    pk.h[1] = __float2bfloat16(q1);
    pk.h[2] = __float2bfloat16(q2);
    pk.h[3] = __float2bfloat16(q3);
    ((uint2*)g_q)[i] = pk.u;
}

// ---------------- kernel 4: build W tile per (j,k) with tensor cores ----------------
// D_p = Ysign_p @ Zsign_p (128x128x16, exact integers via fp32-accum bf16 MMA),
// w = c00*D0 + c01*D1 + sB[m] + sZr[n] + a3s, split into bf16 hi/lo, packed stores.
#define YPITCH 24    // bf16 units per sY row (48 B)
#define ZPITCH 136   // bf16 units per sZ row (272 B)

__global__ void __launch_bounds__(256) k_buildw(const float* __restrict__ Ysign,
                                                const float* __restrict__ Zsign,
                                                const float* __restrict__ Yscale,
                                                const float* __restrict__ Zscale,
                                                const float* __restrict__ Aq) {
    __shared__ __nv_bfloat16 sY[2][MM * YPITCH];   // [p][m*24 + l], 12288 B
    __shared__ __nv_bfloat16 sZ[2][LL * ZPITCH];   // [p][l*136 + n], 8704 B
    __shared__ float sB[MM];
    __shared__ float sZr[NN];

    const int j = blockIdx.x >> 5;
    const int k = blockIdx.x & 31;
    const int tid = threadIdx.x;
    const int lane = tid & 31;
    const int wid = tid >> 5;

    float ysc[2], zsc[2], a0c[2], a1c[2], a2c[2];
    float a3s = 0.f;
#pragma unroll
    for (int p = 0; p < 2; p++) {
        int idx = (p * JJ + j) * KK + k;
        ysc[p] = Yscale[idx]; zsc[p] = Zscale[idx];
        a0c[p] = Aq[idx * 4 + 0]; a1c[p] = Aq[idx * 4 + 1];
        a2c[p] = Aq[idx * 4 + 2]; a3s += Aq[idx * 4 + 3];
        size_t base = (size_t)idx * (MM * LL);   // 2048 floats (== LL*NN)
        const float4* ys4 = (const float4*)(Ysign + base);
        const float4* zs4 = (const float4*)(Zsign + base);
#pragma unroll
        for (int i = 0; i < 2; i++) {
            int e4 = tid + i * 256;            // 0..511
            int e = e4 * 4;
            // Y: (m,l) with l fastest, 16 per row
            float4 v = ys4[e4];
            int m = e >> 4, l = e & 15;
            __nv_bfloat162* dy = (__nv_bfloat162*)(&sY[p][m * YPITCH + l]);
            dy[0] = __nv_bfloat162{__float2bfloat16(v.x), __float2bfloat16(v.y)};
            dy[1] = __nv_bfloat162{__float2bfloat16(v.z), __float2bfloat16(v.w)};
            // Z: (l,n) with n fastest, 128 per row
            float4 w4 = zs4[e4];
            int zl = e >> 7, n = e & 127;
            __nv_bfloat162* dz = (__nv_bfloat162*)(&sZ[p][zl * ZPITCH + n]);
            dz[0] = __nv_bfloat162{__float2bfloat16(w4.x), __float2bfloat16(w4.y)};
            dz[1] = __nv_bfloat162{__float2bfloat16(w4.z), __float2bfloat16(w4.w)};
        }
    }
    __syncthreads();

    // row/col sign sums -> coefficient vectors
    if (tid < 128) {
        int m = tid; float s0 = 0.f, s1 = 0.f;
#pragma unroll
        for (int l = 0; l < 16; l++) {
            s0 += __bfloat162float(sY[0][m * YPITCH + l]);
            s1 += __bfloat162float(sY[1][m * YPITCH + l]);
        }
        sB[m] = a1c[0] * ysc[0] * s0 + a1c[1] * ysc[1] * s1;
    } else {
        int n = tid - 128; float s0 = 0.f, s1 = 0.f;
#pragma unroll
        for (int l = 0; l < 16; l++) {
            s0 += __bfloat162float(sZ[0][l * ZPITCH + n]);
            s1 += __bfloat162float(sZ[1][l * ZPITCH + n]);
        }
        sZr[n] = a2c[0] * zsc[0] * s0 + a2c[1] * zsc[1] * s1;
    }
    __syncthreads();

    const float c00 = a0c[0] * ysc[0] * zsc[0];
    const float c01 = a0c[1] * ysc[1] * zsc[1];
    const int mb = wid * 16;   // warp's m strip

    // A fragments (16x16, row-major m x l), one per p, loaded once
    uint32_t aoff = (uint32_t)((mb + (lane & 15)) * (YPITCH * 2)) + (uint32_t)((lane >> 4) * 16);
    uint32_t af0[4], af1[4];
    ldsm4(af0, smem_u32(&sY[0][0]) + aoff);
    ldsm4(af1, smem_u32(&sY[1][0]) + aoff);

    // B trans-ldsm lane addressing: source rows = l (k dim), cols = n
    uint32_t zoff = (uint32_t)((lane & 15) * (ZPITCH * 2)) + (uint32_t)(((lane >> 4) * 8) * 2);
    const uint32_t zb0 = smem_u32(&sZ[0][0]) + zoff;
    const uint32_t zb1 = smem_u32(&sZ[1][0]) + zoff;

    const int r0 = mb + (lane >> 2);
    const int r1 = r0 + 8;
    const float sb0 = sB[r0];
    const float sb1 = sB[r1];
    __nv_bfloat16* hi0base = g_Whi + (size_t)(j * 128 + r0) * KN + k * 128;
    __nv_bfloat16* hi1base = g_Whi + (size_t)(j * 128 + r1) * KN + k * 128;
    __nv_bfloat16* lo0base = g_Wlo + (size_t)(j * 128 + r0) * KN + k * 128;
    __nv_bfloat16* lo1base = g_Wlo + (size_t)(j * 128 + r1) * KN + k * 128;

#pragma unroll
    for (int nc = 0; nc < 4; nc++) {
        const int n0 = nc * 32;
        uint32_t b0a[4], b0b[4], b1a[4], b1b[4];
        ldsm4t(b0a, zb0 + (uint32_t)(n0 * 2));          // p0, n-tiles 0,1
        ldsm4t(b0b, zb0 + (uint32_t)((n0 + 16) * 2));   // p0, n-tiles 2,3
        ldsm4t(b1a, zb1 + (uint32_t)(n0 * 2));
        ldsm4t(b1b, zb1 + (uint32_t)((n0 + 16) * 2));

        float acc0[4][4], acc1[4][4];
#pragma unroll
        for (int t = 0; t < 4; t++)
#pragma unroll
            for (int v = 0; v < 4; v++) { acc0[t][v] = 0.f; acc1[t][v] = 0.f; }

        mma16816(acc0[0], af0, &b0a[0]); mma16816(acc0[1], af0, &b0a[2]);
        mma16816(acc0[2], af0, &b0b[0]); mma16816(acc0[3], af0, &b0b[2]);
        mma16816(acc1[0], af1, &b1a[0]); mma16816(acc1[1], af1, &b1a[2]);
        mma16816(acc1[2], af1, &b1b[0]); mma16816(acc1[3], af1, &b1b[2]);

#pragma unroll
        for (int nt = 0; nt < 4; nt++) {
            const int col = n0 + nt * 8 + (lane & 3) * 2;
            const float2 zr = *(const float2*)(&sZr[col]);
            const float add0 = zr.x + a3s;
            const float add1 = zr.y + a3s;
            float w00 = c00 * acc0[nt][0] + c01 * acc1[nt][0] + sb0 + add0;
            float w01 = c00 * acc0[nt][1] + c01 * acc1[nt][1] + sb0 + add1;
            float w10 = c00 * acc0[nt][2] + c01 * acc1[nt][2] + sb1 + add0;
            float w11 = c00 * acc0[nt][3] + c01 * acc1[nt][3] + sb1 + add1;

            __nv_bfloat16 h00 = __float2bfloat16(w00), h01 = __float2bfloat16(w01);
            __nv_bfloat16 h10 = __float2bfloat16(w10), h11 = __float2bfloat16(w11);
            __nv_bfloat16 l00 = __float2bfloat16(w00 - __bfloat162float(h00));
            __nv_bfloat16 l01 = __float2bfloat16(w01 - __bfloat162float(h01));
            __nv_bfloat16 l10 = __float2bfloat16(w10 - __bfloat162float(h10));
            __nv_bfloat16 l11 = __float2bfloat16(w11 - __bfloat162float(h11));

            union { __nv_bfloat16 h[2]; uint32_t u; } pk;
            pk.h[0] = h00; pk.h[1] = h01; *(uint32_t*)(hi0base + col) = pk.u;
            pk.h[0] = h10; pk.h[1] = h11; *(uint32_t*)(hi1base + col) = pk.u;
            pk.h[0] = l00; pk.h[1] = l01; *(uint32_t*)(lo0base + col) = pk.u;
            pk.h[0] = l10; pk.h[1] = l11; *(uint32_t*)(lo1base + col) = pk.u;
        }
    }
}

// ---------------- kernel 5: warp-MMA GEMM out = act*(q @ (Whi+Wlo)^T) + bias ----------------
// CTA: 256 threads = 8 warps (4 m x 2 n). CTA tile 128(b) x 128(jm), K-chunk 64.
// 3-stage cp.async pipeline, ONE __syncthreads per chunk.
// Stage layout: A @+0 (16KB), Bhi @+16KB, Blo @+32KB; 128B rows XOR-swizzled.
__global__ void __launch_bounds__(256, 1) k_gemm(const float* __restrict__ bias,
                                                 float* __restrict__ out) {
    extern __shared__ char smem[];
    const uint32_t sbase = smem_u32(smem);

    const int tid = threadIdx.x;
    const int lane = tid & 31;
    const int wid = tid >> 5;
    const int jt = blockIdx.x;        // jm tile, 0..31
    const int bt = blockIdx.y;        // b tile,  0..3
    const int warp_m = wid >> 1;      // 0..3 -> m base warp_m*32
    const int warp_n = wid & 1;       // 0..1 -> n base warp_n*64

    // ---- cp.async source/dest offsets: 4 x 16B chunks per tile per thread ----
    uint32_t swoff[4];
    const char* srcq[4];
    const char* srch[4];
    const char* srcl[4];
    {
        const char* gq  = (const char*)(g_q   + (size_t)(bt * 128) * KN);
        const char* ghi = (const char*)(g_Whi + (size_t)(jt * 128) * KN);
        const char* glo = (const char*)(g_Wlo + (size_t)(jt * 128) * KN);
#pragma unroll
        for (int i = 0; i < 4; i++) {
            int idx = tid + i * 256;            // 0..1023
            int row = idx >> 3;                 // 0..127
            int seg = (idx & 7) * 16;           // byte within 128B row
            swoff[i] = (uint32_t)(row * 128) + ((uint32_t)seg ^ (uint32_t)((row & 7) << 4));
            size_t gb = (size_t)row * (KN * 2) + seg;   // row stride 8192 B
            srcq[i] = gq + gb;
            srch[i] = ghi + gb;
            srcl[i] = glo + gb;
        }
    }

    // ---- prefetch chunks 0 and 1 ----
#pragma unroll
    for (int s = 0; s < 2; s++) {
        uint32_t base = sbase + s * STAGE;
        size_t koff = (size_t)s * 128;          // 64 bf16 = 128 bytes
#pragma unroll
        for (int i = 0; i < 4; i++) {
            cp16(base +         swoff[i], srcq[i] + koff);
            cp16(base + 16384 + swoff[i], srch[i] + koff);
            cp16(base + 32768 + swoff[i], srcl[i] + koff);
        }
        CP_COMMIT();
    }

    // ---- ldmatrix lane addressing ----
    const int a_row = warp_m * 32 + (lane & 15);           // + mt*16
    const uint32_t a_hi  = (uint32_t)((lane >> 4) * 16);
    const uint32_t a_swz = (uint32_t)((a_row & 7) << 4);   // invariant under +16
    const int b_g = lane >> 3;                              // 0..3
    const int b_row0 = warp_n * 64 + ((b_g >> 1) << 3) + (lane & 7);  // + i*16
    const uint32_t b_hi  = (uint32_t)((b_g & 1) * 16);
    const uint32_t b_swz = (uint32_t)((b_row0 & 7) << 4);  // invariant under +16

    float acc[2][8][4];
#pragma unroll
    for (int mt = 0; mt < 2; mt++)
#pragma unroll
        for (int nt = 0; nt < 8; nt++)
#pragma unroll
            for (int v = 0; v < 4; v++) acc[mt][nt][v] = 0.f;

    for (int c = 0; c < NCHUNK; c++) {
        CP_WAIT(1);              // chunk c landed (only c+1's group may remain)
        __syncthreads();         // all threads see chunk c AND finished compute(c-1)

        // issue chunk c+2 into buffer (c+2)%3 == (c-1)%3, freed by the barrier above
        if (c + 2 < NCHUNK) {
            uint32_t base = sbase + ((c + 2) % 3) * STAGE;
            size_t koff = (size_t)(c + 2) * 128;
#pragma unroll
            for (int i = 0; i < 4; i++) {
                cp16(base +         swoff[i], srcq[i] + koff);
                cp16(base + 16384 + swoff[i], srch[i] + koff);
                cp16(base + 32768 + swoff[i], srcl[i] + koff);
            }
        }
        CP_COMMIT();             // fixed group accounting (empty at tail)

        const uint32_t bb = sbase + (c % 3) * STAGE;
#pragma unroll
        for (int ks = 0; ks < 4; ks++) {
            uint32_t a[2][4];
#pragma unroll
            for (int mt = 0; mt < 2; mt++)
                ldsm4(a[mt], bb + (uint32_t)((a_row + mt * 16) * 128)
                              + (((uint32_t)(ks * 32) + a_hi) ^ a_swz));
            uint32_t bh[8][2], bl[8][2];
#pragma unroll
            for (int i = 0; i < 4; i++) {
                uint32_t ro = (uint32_t)((b_row0 + i * 16) * 128)
                            + (((uint32_t)(ks * 32) + b_hi) ^ b_swz);
                uint32_t r[4];
                ldsm4(r, bb + 16384 + ro);
                bh[2*i][0] = r[0]; bh[2*i][1] = r[1]; bh[2*i+1][0] = r[2]; bh[2*i+1][1] = r[3];
                ldsm4(r, bb + 32768 + ro);
                bl[2*i][0] = r[0]; bl[2*i][1] = r[1]; bl[2*i+1][0] = r[2]; bl[2*i+1][1] = r[3];
            }
#pragma unroll
            for (int mt = 0; mt < 2; mt++)
#pragma unroll
                for (int nt = 0; nt < 8; nt++) {
                    mma16816(acc[mt][nt], a[mt], bh[nt]);
                    mma16816(acc[mt][nt], a[mt], bl[nt]);
                }
        }
    }

    // ---- epilogue: out = acc*act + bias ----
    const float act = g_scale;
    const int orow0 = bt * 128 + warp_m * 32 + (lane >> 2);
    const int ocol0 = jt * 128 + warp_n * 64 + (lane & 3) * 2;
#pragma unroll
    for (int mt = 0; mt < 2; mt++) {
        const int r0 = orow0 + mt * 16;
#pragma unroll
        for (int nt = 0; nt < 8; nt++) {
            const int col = ocol0 + nt * 8;
            const float2 b2 = *(const float2*)(bias + col);
            float2 v0, v1;
            v0.x = acc[mt][nt][0] * act + b2.x;
            v0.y = acc[mt][nt][1] * act + b2.y;
            v1.x = acc[mt][nt][2] * act + b2.x;
            v1.y = acc[mt][nt][3] * act + b2.y;
            *(float2*)(out + (size_t)r0 * JM + col)       = v0;
            *(float2*)(out + (size_t)(r0 + 8) * JM + col) = v1;
        }
    }
}

// ---------------- launcher ----------------
extern "C" void kernel_launch(void* const* d_in, const int* in_sizes, int n_in,
                              void* d_out, int out_size) {
    const float *x = nullptr, *Ys = nullptr, *Zs = nullptr;
    const float *Ysc = nullptr, *Zsc = nullptr, *A = nullptr, *bias = nullptr;
    for (int i = 0; i < n_in; i++) {
        const int s = in_sizes[i];
        const float* p = (const float*)d_in[i];
        if (s == BATCH * KN && !x) x = p;                                        // 2097152
        else if (s == PP * JJ * KK * MM * LL) { if (!Ys) Ys = p; else Zs = p; }  // 4194304 x2
        else if (s == PP * JJ * KK) { if (!Ysc) Ysc = p; else Zsc = p; }         // 2048 x2
        else if (s == PP * JJ * KK * 4) A = p;                                   // 8192
        else if (s == JM) bias = p;                                              // 4096
    }
    float* out = (float*)d_out;

    k_minmax<<<256, 256>>>(x, (BATCH * KN) / 4);
    k_scale<<<1, 256>>>();
    k_quant<<<(BATCH * KN) / 4 / 256, 256>>>(x);
    k_buildw<<<JJ * KK, 256>>>(Ys, Zs, Ysc, Zsc, A);

    const int smem_bytes = 3 * STAGE;   // 147456
    cudaFuncSetAttribute(k_gemm, cudaFuncAttributeMaxDynamicSharedMemorySize, smem_bytes);
    dim3 grid(JM / 128, BATCH / 128);
    k_gemm<<<grid, 256, smem_bytes>>>(bias, out);
}

// round 7
// speedup vs baseline: 1.8006x; 1.5339x over previous
#include <cuda_runtime.h>
#include <cuda_bf16.h>
#include <cuda_fp16.h>
#include <cstdint>

// ---------------- problem dims ----------------
#define PP 2
#define JJ 32
#define KK 32
#define MM 128
#define LL 16
#define NN 128
#define BATCH 512
#define KN 4096
#define JM 4096
#define BKC 64                 // GEMM K-chunk (fp16 elements)
#define NCHUNK (KN / BKC)      // 64
#define STAGE 32768            // bytes per pipeline stage (A 16KB + W 16KB)
#define NSTG 4

// ---------------- device scratch (no cudaMalloc allowed) ----------------
__device__ float g_pmax[256];
__device__ float g_pmin[256];
__device__ float g_scale;
__device__ __half g_q[(size_t)BATCH * KN];       // quantized activations (exact ints, fp16)
__device__ __half g_W[(size_t)JM * KN];          // fp16 weight matrix

// ---------------- PTX helpers (sm_100-safe only) ----------------
__device__ __forceinline__ uint32_t smem_u32(const void* p) {
    uint32_t a;
    asm("{ .reg .u64 t; cvta.to.shared.u64 t, %1; cvt.u32.u64 %0, t; }" : "=r"(a) : "l"(p));
    return a;
}

__device__ __forceinline__ void cp16(uint32_t dst, const void* src) {
    asm volatile("cp.async.cg.shared.global [%0], [%1], 16;\n" :: "r"(dst), "l"(src));
}
#define CP_COMMIT() asm volatile("cp.async.commit_group;\n" ::: "memory")
#define CP_WAIT(n)  asm volatile("cp.async.wait_group %0;\n" :: "n"(n) : "memory")

__device__ __forceinline__ void ldsm4(uint32_t* r, uint32_t addr) {
    asm volatile("ldmatrix.sync.aligned.m8n8.x4.shared.b16 {%0,%1,%2,%3}, [%4];"
        : "=r"(r[0]), "=r"(r[1]), "=r"(r[2]), "=r"(r[3]) : "r"(addr));
}
__device__ __forceinline__ void ldsm4t(uint32_t* r, uint32_t addr) {
    asm volatile("ldmatrix.sync.aligned.m8n8.x4.trans.shared.b16 {%0,%1,%2,%3}, [%4];"
        : "=r"(r[0]), "=r"(r[1]), "=r"(r[2]), "=r"(r[3]) : "r"(addr));
}

// bf16 MMA (used in buildw where operands are exact small integers)
__device__ __forceinline__ void mma16816_bf(float* c, const uint32_t* a, const uint32_t* b) {
    asm volatile(
        "mma.sync.aligned.m16n8k16.row.col.f32.bf16.bf16.f32 "
        "{%0,%1,%2,%3}, {%4,%5,%6,%7}, {%8,%9}, {%0,%1,%2,%3};"
        : "+f"(c[0]), "+f"(c[1]), "+f"(c[2]), "+f"(c[3])
        : "r"(a[0]), "r"(a[1]), "r"(a[2]), "r"(a[3]), "r"(b[0]), "r"(b[1]));
}
// fp16 MMA with fp32 accum (main GEMM)
__device__ __forceinline__ void mma16816_f16(float* c, const uint32_t* a, const uint32_t* b) {
    asm volatile(
        "mma.sync.aligned.m16n8k16.row.col.f32.f16.f16.f32 "
        "{%0,%1,%2,%3}, {%4,%5,%6,%7}, {%8,%9}, {%0,%1,%2,%3};"
        : "+f"(c[0]), "+f"(c[1]), "+f"(c[2]), "+f"(c[3])
        : "r"(a[0]), "r"(a[1]), "r"(a[2]), "r"(a[3]), "r"(b[0]), "r"(b[1]));
}

// ---------------- kernel 1: per-block min/max partials ----------------
__global__ void __launch_bounds__(256) k_minmax(const float* __restrict__ x, int n4) {
    const float4* x4 = (const float4*)x;
    float mx = -3.4e38f, mn = 3.4e38f;
    for (int i = blockIdx.x * blockDim.x + threadIdx.x; i < n4; i += gridDim.x * blockDim.x) {
        float4 v = x4[i];
        mx = fmaxf(mx, fmaxf(fmaxf(v.x, v.y), fmaxf(v.z, v.w)));
        mn = fminf(mn, fminf(fminf(v.x, v.y), fminf(v.z, v.w)));
    }
    __shared__ float smx[256], smn[256];
    int t = threadIdx.x;
    smx[t] = mx; smn[t] = mn;
    __syncthreads();
    for (int s = 128; s > 0; s >>= 1) {
        if (t < s) { smx[t] = fmaxf(smx[t], smx[t + s]); smn[t] = fminf(smn[t], smn[t + s]); }
        __syncthreads();
    }
    if (t == 0) { g_pmax[blockIdx.x] = smx[0]; g_pmin[blockIdx.x] = smn[0]; }
}

// ---------------- kernel 2: finalize act_scale ----------------
__global__ void __launch_bounds__(256) k_scale() {
    __shared__ float smx[256], smn[256];
    int t = threadIdx.x;
    smx[t] = g_pmax[t]; smn[t] = g_pmin[t];
    __syncthreads();
    for (int s = 128; s > 0; s >>= 1) {
        if (t < s) { smx[t] = fmaxf(smx[t], smx[t + s]); smn[t] = fminf(smn[t], smn[t + s]); }
        __syncthreads();
    }
    if (t == 0) {
        float s = __fdiv_rn(smx[0] - smn[0], 254.0f);   // (max-min)/(2*qmax), qmax=127
        g_scale = fmaxf(s, 1e-8f);
    }
}

// ---------------- kernel 3: quantize activations to exact fp16 integers ----------------
__global__ void __launch_bounds__(256) k_quant(const float* __restrict__ x) {
    float s = g_scale;
    int i = blockIdx.x * blockDim.x + threadIdx.x;   // one float4 per thread
    const float4* x4 = (const float4*)x;
    float4 v = x4[i];
    float q0 = fminf(fmaxf(rintf(__fdiv_rn(v.x, s)), -127.f), 127.f);
    float q1 = fminf(fmaxf(rintf(__fdiv_rn(v.y, s)), -127.f), 127.f);
    float q2 = fminf(fmaxf(rintf(__fdiv_rn(v.z, s)), -127.f), 127.f);
    float q3 = fminf(fmaxf(rintf(__fdiv_rn(v.w, s)), -127.f), 127.f);
    union { __half h[4]; uint2 u; } pk;
    pk.h[0] = __float2half_rn(q0);
    pk.h[1] = __float2half_rn(q1);
    pk.h[2] = __float2half_rn(q2);
    pk.h[3] = __float2half_rn(q3);
    ((uint2*)g_q)[i] = pk.u;
}

// ---------------- kernel 4: build W tile per (j,k) with tensor cores ----------------
// D_p = Ysign_p @ Zsign_p (128x128x16, exact integers via fp32-accum bf16 MMA),
// w = c00*D0 + c01*D1 + sB[m] + sZr[n] + a3s, stored as packed fp16.
#define YPITCH 24    // bf16 units per sY row (48 B)
#define ZPITCH 136   // bf16 units per sZ row (272 B)

__global__ void __launch_bounds__(256) k_buildw(const float* __restrict__ Ysign,
                                                const float* __restrict__ Zsign,
                                                const float* __restrict__ Yscale,
                                                const float* __restrict__ Zscale,
                                                const float* __restrict__ Aq) {
    __shared__ __nv_bfloat16 sY[2][MM * YPITCH];   // [p][m*24 + l]
    __shared__ __nv_bfloat16 sZ[2][LL * ZPITCH];   // [p][l*136 + n]
    __shared__ float sB[MM];
    __shared__ float sZr[NN];

    const int j = blockIdx.x >> 5;
    const int k = blockIdx.x & 31;
    const int tid = threadIdx.x;
    const int lane = tid & 31;
    const int wid = tid >> 5;

    float ysc[2], zsc[2], a0c[2], a1c[2], a2c[2];
    float a3s = 0.f;
#pragma unroll
    for (int p = 0; p < 2; p++) {
        int idx = (p * JJ + j) * KK + k;
        ysc[p] = Yscale[idx]; zsc[p] = Zscale[idx];
        a0c[p] = Aq[idx * 4 + 0]; a1c[p] = Aq[idx * 4 + 1];
        a2c[p] = Aq[idx * 4 + 2]; a3s += Aq[idx * 4 + 3];
        size_t base = (size_t)idx * (MM * LL);   // 2048 floats (== LL*NN)
        const float4* ys4 = (const float4*)(Ysign + base);
        const float4* zs4 = (const float4*)(Zsign + base);
#pragma unroll
        for (int i = 0; i < 2; i++) {
            int e4 = tid + i * 256;            // 0..511
            int e = e4 * 4;
            // Y: (m,l) with l fastest, 16 per row
            float4 v = ys4[e4];
            int m = e >> 4, l = e & 15;
            __nv_bfloat162* dy = (__nv_bfloat162*)(&sY[p][m * YPITCH + l]);
            dy[0] = __nv_bfloat162{__float2bfloat16(v.x), __float2bfloat16(v.y)};
            dy[1] = __nv_bfloat162{__float2bfloat16(v.z), __float2bfloat16(v.w)};
            // Z: (l,n) with n fastest, 128 per row
            float4 w4 = zs4[e4];
            int zl = e >> 7, n = e & 127;
            __nv_bfloat162* dz = (__nv_bfloat162*)(&sZ[p][zl * ZPITCH + n]);
            dz[0] = __nv_bfloat162{__float2bfloat16(w4.x), __float2bfloat16(w4.y)};
            dz[1] = __nv_bfloat162{__float2bfloat16(w4.z), __float2bfloat16(w4.w)};
        }
    }
    __syncthreads();

    // row/col sign sums -> coefficient vectors
    if (tid < 128) {
        int m = tid; float s0 = 0.f, s1 = 0.f;
#pragma unroll
        for (int l = 0; l < 16; l++) {
            s0 += __bfloat162float(sY[0][m * YPITCH + l]);
            s1 += __bfloat162float(sY[1][m * YPITCH + l]);
        }
        sB[m] = a1c[0] * ysc[0] * s0 + a1c[1] * ysc[1] * s1;
    } else {
        int n = tid - 128; float s0 = 0.f, s1 = 0.f;
#pragma unroll
        for (int l = 0; l < 16; l++) {
            s0 += __bfloat162float(sZ[0][l * ZPITCH + n]);
            s1 += __bfloat162float(sZ[1][l * ZPITCH + n]);
        }
        sZr[n] = a2c[0] * zsc[0] * s0 + a2c[1] * zsc[1] * s1;
    }
    __syncthreads();

    const float c00 = a0c[0] * ysc[0] * zsc[0];
    const float c01 = a0c[1] * ysc[1] * zsc[1];
    const int mb = wid * 16;   // warp's m strip

    // A fragments (16x16, row-major m x l), one per p, loaded once
    uint32_t aoff = (uint32_t)((mb + (lane & 15)) * (YPITCH * 2)) + (uint32_t)((lane >> 4) * 16);
    uint32_t af0[4], af1[4];
    ldsm4(af0, smem_u32(&sY[0][0]) + aoff);
    ldsm4(af1, smem_u32(&sY[1][0]) + aoff);

    // B trans-ldsm lane addressing: source rows = l (k dim), cols = n
    uint32_t zoff = (uint32_t)((lane & 15) * (ZPITCH * 2)) + (uint32_t)(((lane >> 4) * 8) * 2);
    const uint32_t zb0 = smem_u32(&sZ[0][0]) + zoff;
    const uint32_t zb1 = smem_u32(&sZ[1][0]) + zoff;

    const int r0 = mb + (lane >> 2);
    const int r1 = r0 + 8;
    const float sb0 = sB[r0];
    const float sb1 = sB[r1];
    __half* w0base = g_W + (size_t)(j * 128 + r0) * KN + k * 128;
    __half* w1base = g_W + (size_t)(j * 128 + r1) * KN + k * 128;

#pragma unroll
    for (int nc = 0; nc < 4; nc++) {
        const int n0 = nc * 32;
        uint32_t b0a[4], b0b[4], b1a[4], b1b[4];
        ldsm4t(b0a, zb0 + (uint32_t)(n0 * 2));          // p0, n-tiles 0,1
        ldsm4t(b0b, zb0 + (uint32_t)((n0 + 16) * 2));   // p0, n-tiles 2,3
        ldsm4t(b1a, zb1 + (uint32_t)(n0 * 2));
        ldsm4t(b1b, zb1 + (uint32_t)((n0 + 16) * 2));

        float acc0[4][4], acc1[4][4];
#pragma unroll
        for (int t = 0; t < 4; t++)
#pragma unroll
            for (int v = 0; v < 4; v++) { acc0[t][v] = 0.f; acc1[t][v] = 0.f; }

        mma16816_bf(acc0[0], af0, &b0a[0]); mma16816_bf(acc0[1], af0, &b0a[2]);
        mma16816_bf(acc0[2], af0, &b0b[0]); mma16816_bf(acc0[3], af0, &b0b[2]);
        mma16816_bf(acc1[0], af1, &b1a[0]); mma16816_bf(acc1[1], af1, &b1a[2]);
        mma16816_bf(acc1[2], af1, &b1b[0]); mma16816_bf(acc1[3], af1, &b1b[2]);

#pragma unroll
        for (int nt = 0; nt < 4; nt++) {
            const int col = n0 + nt * 8 + (lane & 3) * 2;
            const float2 zr = *(const float2*)(&sZr[col]);
            const float add0 = zr.x + a3s;
            const float add1 = zr.y + a3s;
            float w00 = c00 * acc0[nt][0] + c01 * acc1[nt][0] + sb0 + add0;
            float w01 = c00 * acc0[nt][1] + c01 * acc1[nt][1] + sb0 + add1;
            float w10 = c00 * acc0[nt][2] + c01 * acc1[nt][2] + sb1 + add0;
            float w11 = c00 * acc0[nt][3] + c01 * acc1[nt][3] + sb1 + add1;

            union { __half h[2]; uint32_t u; } pk;
            pk.h[0] = __float2half_rn(w00); pk.h[1] = __float2half_rn(w01);
            *(uint32_t*)(w0base + col) = pk.u;
            pk.h[0] = __float2half_rn(w10); pk.h[1] = __float2half_rn(w11);
            *(uint32_t*)(w1base + col) = pk.u;
        }
    }
}

// ---------------- kernel 5: warp-MMA GEMM out = act*(q @ W^T) + bias ----------------
// CTA: 256 threads = 8 warps (4 m x 2 n). CTA tile 128(b) x 128(jm), K-chunk 64.
// 4-stage cp.async pipeline, one __syncthreads per chunk.
// Stage: A @+0 (16KB), W @+16KB; 128B rows XOR-swizzled for conflict-free ldmatrix.
__global__ void __launch_bounds__(256, 1) k_gemm(const float* __restrict__ bias,
                                                 float* __restrict__ out) {
    extern __shared__ char smem[];
    const uint32_t sbase = smem_u32(smem);

    const int tid = threadIdx.x;
    const int lane = tid & 31;
    const int wid = tid >> 5;
    const int jt = blockIdx.x;        // jm tile, 0..31
    const int bt = blockIdx.y;        // b tile,  0..3
    const int warp_m = wid >> 1;      // 0..3 -> m base warp_m*32
    const int warp_n = wid & 1;       // 0..1 -> n base warp_n*64

    // ---- cp.async source/dest offsets: 4 x 16B chunks per tile per thread ----
    uint32_t swoff[4];
    const char* srcq[4];
    const char* srcw[4];
    {
        const char* gq = (const char*)(g_q + (size_t)(bt * 128) * KN);
        const char* gw = (const char*)(g_W + (size_t)(jt * 128) * KN);
#pragma unroll
        for (int i = 0; i < 4; i++) {
            int idx = tid + i * 256;            // 0..1023
            int row = idx >> 3;                 // 0..127
            int seg = (idx & 7) * 16;           // byte within 128B row
            swoff[i] = (uint32_t)(row * 128) + ((uint32_t)seg ^ (uint32_t)((row & 7) << 4));
            size_t gb = (size_t)row * (KN * 2) + seg;   // row stride 8192 B
            srcq[i] = gq + gb;
            srcw[i] = gw + gb;
        }
    }

    // ---- prefetch chunks 0..2 ----
#pragma unroll
    for (int s = 0; s < NSTG - 1; s++) {
        uint32_t base = sbase + s * STAGE;
        size_t koff = (size_t)s * 128;          // 64 fp16 = 128 bytes
#pragma unroll
        for (int i = 0; i < 4; i++) {
            cp16(base +         swoff[i], srcq[i] + koff);
            cp16(base + 16384 + swoff[i], srcw[i] + koff);
        }
        CP_COMMIT();
    }

    // ---- ldmatrix lane addressing ----
    const int a_row = warp_m * 32 + (lane & 15);           // + mt*16
    const uint32_t a_hi  = (uint32_t)((lane >> 4) * 16);
    const uint32_t a_swz = (uint32_t)((a_row & 7) << 4);   // invariant under +16
    const int b_g = lane >> 3;                              // 0..3
    const int b_row0 = warp_n * 64 + ((b_g >> 1) << 3) + (lane & 7);  // + i*16
    const uint32_t b_hi  = (uint32_t)((b_g & 1) * 16);
    const uint32_t b_swz = (uint32_t)((b_row0 & 7) << 4);  // invariant under +16

    float acc[2][8][4];
#pragma unroll
    for (int mt = 0; mt < 2; mt++)
#pragma unroll
        for (int nt = 0; nt < 8; nt++)
#pragma unroll
            for (int v = 0; v < 4; v++) acc[mt][nt][v] = 0.f;

    for (int c = 0; c < NCHUNK; c++) {
        CP_WAIT(2);              // chunk c landed (chunks c+1, c+2 may remain)
        __syncthreads();         // all threads see chunk c AND finished compute(c-1)

        // issue chunk c+3 into buffer (c+3)%4 == (c-1)%4, freed by the barrier above
        if (c + 3 < NCHUNK) {
            uint32_t base = sbase + ((c + 3) % NSTG) * STAGE;
            size_t koff = (size_t)(c + 3) * 128;
#pragma unroll
            for (int i = 0; i < 4; i++) {
                cp16(base +         swoff[i], srcq[i] + koff);
                cp16(base + 16384 + swoff[i], srcw[i] + koff);
            }
        }
        CP_COMMIT();             // fixed group accounting (empty at tail)

        const uint32_t bb = sbase + (c % NSTG) * STAGE;
#pragma unroll
        for (int ks = 0; ks < 4; ks++) {
            uint32_t a[2][4];
#pragma unroll
            for (int mt = 0; mt < 2; mt++)
                ldsm4(a[mt], bb + (uint32_t)((a_row + mt * 16) * 128)
                              + (((uint32_t)(ks * 32) + a_hi) ^ a_swz));
            uint32_t bw[8][2];
#pragma unroll
            for (int i = 0; i < 4; i++) {
                uint32_t ro = (uint32_t)((b_row0 + i * 16) * 128)
                            + (((uint32_t)(ks * 32) + b_hi) ^ b_swz);
                uint32_t r[4];
                ldsm4(r, bb + 16384 + ro);
                bw[2*i][0] = r[0]; bw[2*i][1] = r[1]; bw[2*i+1][0] = r[2]; bw[2*i+1][1] = r[3];
            }
#pragma unroll
            for (int mt = 0; mt < 2; mt++)
#pragma unroll
                for (int nt = 0; nt < 8; nt++)
                    mma16816_f16(acc[mt][nt], a[mt], bw[nt]);
        }
    }

    // ---- epilogue: out = acc*act + bias ----
    const float act = g_scale;
    const int orow0 = bt * 128 + warp_m * 32 + (lane >> 2);
    const int ocol0 = jt * 128 + warp_n * 64 + (lane & 3) * 2;
#pragma unroll
    for (int mt = 0; mt < 2; mt++) {
        const int r0 = orow0 + mt * 16;
#pragma unroll
        for (int nt = 0; nt < 8; nt++) {
            const int col = ocol0 + nt * 8;
            const float2 b2 = *(const float2*)(bias + col);
            float2 v0, v1;
            v0.x = acc[mt][nt][0] * act + b2.x;
            v0.y = acc[mt][nt][1] * act + b2.y;
            v1.x = acc[mt][nt][2] * act + b2.x;
            v1.y = acc[mt][nt][3] * act + b2.y;
            *(float2*)(out + (size_t)r0 * JM + col)       = v0;
            *(float2*)(out + (size_t)(r0 + 8) * JM + col) = v1;
        }
    }
}

// ---------------- launcher ----------------
extern "C" void kernel_launch(void* const* d_in, const int* in_sizes, int n_in,
                              void* d_out, int out_size) {
    const float *x = nullptr, *Ys = nullptr, *Zs = nullptr;
    const float *Ysc = nullptr, *Zsc = nullptr, *A = nullptr, *bias = nullptr;
    for (int i = 0; i < n_in; i++) {
        const int s = in_sizes[i];
        const float* p = (const float*)d_in[i];
        if (s == BATCH * KN && !x) x = p;                                        // 2097152
        else if (s == PP * JJ * KK * MM * LL) { if (!Ys) Ys = p; else Zs = p; }  // 4194304 x2
        else if (s == PP * JJ * KK) { if (!Ysc) Ysc = p; else Zsc = p; }         // 2048 x2
        else if (s == PP * JJ * KK * 4) A = p;                                   // 8192
        else if (s == JM) bias = p;                                              // 4096
    }
    float* out = (float*)d_out;

    k_minmax<<<256, 256>>>(x, (BATCH * KN) / 4);
    k_scale<<<1, 256>>>();
    k_quant<<<(BATCH * KN) / 4 / 256, 256>>>(x);
    k_buildw<<<JJ * KK, 256>>>(Ys, Zs, Ysc, Zsc, A);

    const int smem_bytes = NSTG * STAGE;   // 131072
    cudaFuncSetAttribute(k_gemm, cudaFuncAttributeMaxDynamicSharedMemorySize, smem_bytes);
    dim3 grid(JM / 128, BATCH / 128);
    k_gemm<<<grid, 256, smem_bytes>>>(bias, out);
}

// round 8
// speedup vs baseline: 1.9200x; 1.0663x over previous
#include <cuda_runtime.h>
#include <cuda_bf16.h>
#include <cuda_fp16.h>
#include <cstdint>

// ---------------- problem dims ----------------
#define PP 2
#define JJ 32
#define KK 32
#define MM 128
#define LL 16
#define NN 128
#define BATCH 512
#define KN 4096
#define JM 4096
#define BKC 64                 // GEMM K-chunk (fp16 elements)
#define NCHUNK (KN / BKC)      // 64
#define STAGE 32768            // bytes per pipeline stage (A 16KB + W 16KB)
#define NSTG 4

// ---------------- device scratch (no cudaMalloc allowed) ----------------
__device__ float g_pmax[256];
__device__ float g_pmin[256];
__device__ float g_scale;
__device__ unsigned g_cnt = 0;
__device__ __half g_q[(size_t)BATCH * KN];       // quantized activations (exact ints, fp16)
__device__ __half g_W[(size_t)JM * KN];          // fp16 weight matrix

// ---------------- PTX helpers (sm_100-safe only) ----------------
__device__ __forceinline__ uint32_t smem_u32(const void* p) {
    uint32_t a;
    asm("{ .reg .u64 t; cvta.to.shared.u64 t, %1; cvt.u32.u64 %0, t; }" : "=r"(a) : "l"(p));
    return a;
}

__device__ __forceinline__ void cp16(uint32_t dst, const void* src) {
    asm volatile("cp.async.cg.shared.global [%0], [%1], 16;\n" :: "r"(dst), "l"(src));
}
#define CP_COMMIT() asm volatile("cp.async.commit_group;\n" ::: "memory")
#define CP_WAIT(n)  asm volatile("cp.async.wait_group %0;\n" :: "n"(n) : "memory")

__device__ __forceinline__ void ldsm4(uint32_t* r, uint32_t addr) {
    asm volatile("ldmatrix.sync.aligned.m8n8.x4.shared.b16 {%0,%1,%2,%3}, [%4];"
        : "=r"(r[0]), "=r"(r[1]), "=r"(r[2]), "=r"(r[3]) : "r"(addr));
}
__device__ __forceinline__ void ldsm4t(uint32_t* r, uint32_t addr) {
    asm volatile("ldmatrix.sync.aligned.m8n8.x4.trans.shared.b16 {%0,%1,%2,%3}, [%4];"
        : "=r"(r[0]), "=r"(r[1]), "=r"(r[2]), "=r"(r[3]) : "r"(addr));
}

// bf16 MMA (used in buildw where operands are exact small integers)
__device__ __forceinline__ void mma16816_bf(float* c, const uint32_t* a, const uint32_t* b) {
    asm volatile(
        "mma.sync.aligned.m16n8k16.row.col.f32.bf16.bf16.f32 "
        "{%0,%1,%2,%3}, {%4,%5,%6,%7}, {%8,%9}, {%0,%1,%2,%3};"
        : "+f"(c[0]), "+f"(c[1]), "+f"(c[2]), "+f"(c[3])
        : "r"(a[0]), "r"(a[1]), "r"(a[2]), "r"(a[3]), "r"(b[0]), "r"(b[1]));
}
// fp16 MMA with fp32 accum (main GEMM)
__device__ __forceinline__ void mma16816_f16(float* c, const uint32_t* a, const uint32_t* b) {
    asm volatile(
        "mma.sync.aligned.m16n8k16.row.col.f32.f16.f16.f32 "
        "{%0,%1,%2,%3}, {%4,%5,%6,%7}, {%8,%9}, {%0,%1,%2,%3};"
        : "+f"(c[0]), "+f"(c[1]), "+f"(c[2]), "+f"(c[3])
        : "r"(a[0]), "r"(a[1]), "r"(a[2]), "r"(a[3]), "r"(b[0]), "r"(b[1]));
}

// ---------------- kernel 1: min/max partials + last-block finalize ----------------
__global__ void __launch_bounds__(256) k_minmax(const float* __restrict__ x, int n4) {
    const float4* x4 = (const float4*)x;
    float mx = -3.4e38f, mn = 3.4e38f;
    for (int i = blockIdx.x * blockDim.x + threadIdx.x; i < n4; i += gridDim.x * blockDim.x) {
        float4 v = x4[i];
        mx = fmaxf(mx, fmaxf(fmaxf(v.x, v.y), fmaxf(v.z, v.w)));
        mn = fminf(mn, fminf(fminf(v.x, v.y), fminf(v.z, v.w)));
    }
    __shared__ float smx[256], smn[256];
    __shared__ int s_last;
    int t = threadIdx.x;
    smx[t] = mx; smn[t] = mn;
    __syncthreads();
    for (int s = 128; s > 0; s >>= 1) {
        if (t < s) { smx[t] = fmaxf(smx[t], smx[t + s]); smn[t] = fminf(smn[t], smn[t + s]); }
        __syncthreads();
    }
    if (t == 0) {
        g_pmax[blockIdx.x] = smx[0];
        g_pmin[blockIdx.x] = smn[0];
        __threadfence();
        unsigned old = atomicAdd(&g_cnt, 1);
        s_last = (old == gridDim.x - 1);
    }
    __syncthreads();
    if (s_last) {
        __threadfence();
        smx[t] = g_pmax[t]; smn[t] = g_pmin[t];
        __syncthreads();
        for (int s = 128; s > 0; s >>= 1) {
            if (t < s) { smx[t] = fmaxf(smx[t], smx[t + s]); smn[t] = fminf(smn[t], smn[t + s]); }
            __syncthreads();
        }
        if (t == 0) {
            float s = __fdiv_rn(smx[0] - smn[0], 254.0f);   // (max-min)/(2*qmax), qmax=127
            g_scale = fmaxf(s, 1e-8f);
            g_cnt = 0;                                       // reset for graph replay
        }
    }
}

// ---------------- kernel 3: quantize activations to exact fp16 integers ----------------
__global__ void __launch_bounds__(256) k_quant(const float* __restrict__ x) {
    float s = g_scale;
    int i = blockIdx.x * blockDim.x + threadIdx.x;   // one float4 per thread
    const float4* x4 = (const float4*)x;
    float4 v = x4[i];
    float q0 = fminf(fmaxf(rintf(__fdiv_rn(v.x, s)), -127.f), 127.f);
    float q1 = fminf(fmaxf(rintf(__fdiv_rn(v.y, s)), -127.f), 127.f);
    float q2 = fminf(fmaxf(rintf(__fdiv_rn(v.z, s)), -127.f), 127.f);
    float q3 = fminf(fmaxf(rintf(__fdiv_rn(v.w, s)), -127.f), 127.f);
    union { __half h[4]; uint2 u; } pk;
    pk.h[0] = __float2half_rn(q0);
    pk.h[1] = __float2half_rn(q1);
    pk.h[2] = __float2half_rn(q2);
    pk.h[3] = __float2half_rn(q3);
    ((uint2*)g_q)[i] = pk.u;
}

// ---------------- kernel 4: build W tile per (j,k) with tensor cores ----------------
// D_p = Ysign_p @ Zsign_p (128x128x16, exact integers via fp32-accum bf16 MMA),
// w = c00*D0 + c01*D1 + sB[m] + sZr[n] + a3s, staged in smem, coalesced fp16 stores.
#define YPITCH 24     // bf16 units per sY row (48 B)
#define ZPITCH 136    // bf16 units per sZ row (272 B)
#define OPITCH 136    // fp16 units per sO row (272 B)
#define SY_OFF  0          // bf16 [2][128*24]  = 12288 B
#define SZ_OFF  12288      // bf16 [2][16*136]  = 8704 B
#define SB_OFF  20992      // float[128]        = 512 B
#define SZR_OFF 21504      // float[128]        = 512 B
#define SO_OFF  22016      // half [128][136]   = 34816 B
#define BW_SMEM 56832

__global__ void __launch_bounds__(256) k_buildw(const float* __restrict__ Ysign,
                                                const float* __restrict__ Zsign,
                                                const float* __restrict__ Yscale,
                                                const float* __restrict__ Zscale,
                                                const float* __restrict__ Aq) {
    extern __shared__ char sm[];
    __nv_bfloat16* sY0 = (__nv_bfloat16*)(sm + SY_OFF);
    __nv_bfloat16* sY1 = (__nv_bfloat16*)(sm + SY_OFF + MM * YPITCH * 2);
    __nv_bfloat16* sZ0 = (__nv_bfloat16*)(sm + SZ_OFF);
    __nv_bfloat16* sZ1 = (__nv_bfloat16*)(sm + SZ_OFF + LL * ZPITCH * 2);
    float* sB  = (float*)(sm + SB_OFF);
    float* sZr = (float*)(sm + SZR_OFF);
    uint32_t* sO = (uint32_t*)(sm + SO_OFF);   // addressed in uint32 units

    const int j = blockIdx.x >> 5;
    const int k = blockIdx.x & 31;
    const int tid = threadIdx.x;
    const int lane = tid & 31;
    const int wid = tid >> 5;

    float ysc[2], zsc[2], a0c[2], a1c[2], a2c[2];
    float a3s = 0.f;
#pragma unroll
    for (int p = 0; p < 2; p++) {
        int idx = (p * JJ + j) * KK + k;
        ysc[p] = Yscale[idx]; zsc[p] = Zscale[idx];
        a0c[p] = Aq[idx * 4 + 0]; a1c[p] = Aq[idx * 4 + 1];
        a2c[p] = Aq[idx * 4 + 2]; a3s += Aq[idx * 4 + 3];
        size_t base = (size_t)idx * (MM * LL);   // 2048 floats (== LL*NN)
        const float4* ys4 = (const float4*)(Ysign + base);
        const float4* zs4 = (const float4*)(Zsign + base);
        __nv_bfloat16* sYp = p ? sY1 : sY0;
        __nv_bfloat16* sZp = p ? sZ1 : sZ0;
#pragma unroll
        for (int i = 0; i < 2; i++) {
            int e4 = tid + i * 256;            // 0..511
            int e = e4 * 4;
            // Y: (m,l) with l fastest, 16 per row
            float4 v = ys4[e4];
            int m = e >> 4, l = e & 15;
            __nv_bfloat162* dy = (__nv_bfloat162*)(&sYp[m * YPITCH + l]);
            dy[0] = __nv_bfloat162{__float2bfloat16(v.x), __float2bfloat16(v.y)};
            dy[1] = __nv_bfloat162{__float2bfloat16(v.z), __float2bfloat16(v.w)};
            // Z: (l,n) with n fastest, 128 per row
            float4 w4 = zs4[e4];
            int zl = e >> 7, n = e & 127;
            __nv_bfloat162* dz = (__nv_bfloat162*)(&sZp[zl * ZPITCH + n]);
            dz[0] = __nv_bfloat162{__float2bfloat16(w4.x), __float2bfloat16(w4.y)};
            dz[1] = __nv_bfloat162{__float2bfloat16(w4.z), __float2bfloat16(w4.w)};
        }
    }
    __syncthreads();

    // row/col sign sums -> coefficient vectors
    if (tid < 128) {
        int m = tid; float s0 = 0.f, s1 = 0.f;
#pragma unroll
        for (int l = 0; l < 16; l++) {
            s0 += __bfloat162float(sY0[m * YPITCH + l]);
            s1 += __bfloat162float(sY1[m * YPITCH + l]);
        }
        sB[m] = a1c[0] * ysc[0] * s0 + a1c[1] * ysc[1] * s1;
    } else {
        int n = tid - 128; float s0 = 0.f, s1 = 0.f;
#pragma unroll
        for (int l = 0; l < 16; l++) {
            s0 += __bfloat162float(sZ0[l * ZPITCH + n]);
            s1 += __bfloat162float(sZ1[l * ZPITCH + n]);
        }
        sZr[n] = a2c[0] * zsc[0] * s0 + a2c[1] * zsc[1] * s1;
    }
    __syncthreads();

    const float c00 = a0c[0] * ysc[0] * zsc[0];
    const float c01 = a0c[1] * ysc[1] * zsc[1];
    const int mb = wid * 16;   // warp's m strip

    // A fragments (16x16, row-major m x l), one per p, loaded once
    uint32_t aoff = (uint32_t)((mb + (lane & 15)) * (YPITCH * 2)) + (uint32_t)((lane >> 4) * 16);
    uint32_t af0[4], af1[4];
    ldsm4(af0, smem_u32(sY0) + aoff);
    ldsm4(af1, smem_u32(sY1) + aoff);

    // B trans-ldsm lane addressing: source rows = l (k dim), cols = n
    uint32_t zoff = (uint32_t)((lane & 15) * (ZPITCH * 2)) + (uint32_t)(((lane >> 4) * 8) * 2);
    const uint32_t zb0 = smem_u32(sZ0) + zoff;
    const uint32_t zb1 = smem_u32(sZ1) + zoff;

    const int r0 = mb + (lane >> 2);
    const int r1 = r0 + 8;
    const float sb0 = sB[r0];
    const float sb1 = sB[r1];
    const int so0 = r0 * (OPITCH / 2);   // uint32 row base
    const int so1 = r1 * (OPITCH / 2);

#pragma unroll
    for (int nc = 0; nc < 4; nc++) {
        const int n0 = nc * 32;
        uint32_t b0a[4], b0b[4], b1a[4], b1b[4];
        ldsm4t(b0a, zb0 + (uint32_t)(n0 * 2));          // p0, n-tiles 0,1
        ldsm4t(b0b, zb0 + (uint32_t)((n0 + 16) * 2));   // p0, n-tiles 2,3
        ldsm4t(b1a, zb1 + (uint32_t)(n0 * 2));
        ldsm4t(b1b, zb1 + (uint32_t)((n0 + 16) * 2));

        float acc0[4][4], acc1[4][4];
#pragma unroll
        for (int t = 0; t < 4; t++)
#pragma unroll
            for (int v = 0; v < 4; v++) { acc0[t][v] = 0.f; acc1[t][v] = 0.f; }

        mma16816_bf(acc0[0], af0, &b0a[0]); mma16816_bf(acc0[1], af0, &b0a[2]);
        mma16816_bf(acc0[2], af0, &b0b[0]); mma16816_bf(acc0[3], af0, &b0b[2]);
        mma16816_bf(acc1[0], af1, &b1a[0]); mma16816_bf(acc1[1], af1, &b1a[2]);
        mma16816_bf(acc1[2], af1, &b1b[0]); mma16816_bf(acc1[3], af1, &b1b[2]);

#pragma unroll
        for (int nt = 0; nt < 4; nt++) {
            const int col = n0 + nt * 8 + (lane & 3) * 2;
            const float2 zr = *(const float2*)(&sZr[col]);
            const float add0 = zr.x + a3s;
            const float add1 = zr.y + a3s;
            float w00 = c00 * acc0[nt][0] + c01 * acc1[nt][0] + sb0 + add0;
            float w01 = c00 * acc0[nt][1] + c01 * acc1[nt][1] + sb0 + add1;
            float w10 = c00 * acc0[nt][2] + c01 * acc1[nt][2] + sb1 + add0;
            float w11 = c00 * acc0[nt][3] + c01 * acc1[nt][3] + sb1 + add1;

            union { __half h[2]; uint32_t u; } pk;
            pk.h[0] = __float2half_rn(w00); pk.h[1] = __float2half_rn(w01);
            sO[so0 + (col >> 1)] = pk.u;
            pk.h[0] = __float2half_rn(w10); pk.h[1] = __float2half_rn(w11);
            sO[so1 + (col >> 1)] = pk.u;
        }
    }
    __syncthreads();

    // coalesced store: 128 rows x 256 B, full 128B lines
    const char* sob = sm + SO_OFF;
    char* gw = (char*)(g_W + (size_t)(j * 128) * KN + k * 128);
#pragma unroll
    for (int it = 0; it < 8; it++) {
        int c = tid + it * 256;         // 0..2047
        int row = c >> 4;
        int seg = c & 15;
        uint4 v = *(const uint4*)(sob + row * (OPITCH * 2) + seg * 16);
        *(uint4*)(gw + (size_t)row * (KN * 2) + seg * 16) = v;
    }
}

// ---------------- kernel 5: warp-MMA GEMM out = act*(q @ W^T) + bias ----------------
// CTA: 256 threads = 8 warps (4 m x 2 n). CTA tile 128(b) x 128(jm), K-chunk 64.
// 4-stage cp.async pipeline, one __syncthreads per chunk.
// Stage: A @+0 (16KB), W @+16KB; 128B rows XOR-swizzled for conflict-free ldmatrix.
__global__ void __launch_bounds__(256, 1) k_gemm(const float* __restrict__ bias,
                                                 float* __restrict__ out) {
    extern __shared__ char smem[];
    const uint32_t sbase = smem_u32(smem);

    const int tid = threadIdx.x;
    const int lane = tid & 31;
    const int wid = tid >> 5;
    const int jt = blockIdx.x;        // jm tile, 0..31
    const int bt = blockIdx.y;        // b tile,  0..3
    const int warp_m = wid >> 1;      // 0..3 -> m base warp_m*32
    const int warp_n = wid & 1;       // 0..1 -> n base warp_n*64

    // ---- cp.async source/dest offsets: 4 x 16B chunks per tile per thread ----
    uint32_t swoff[4];
    const char* srcq[4];
    const char* srcw[4];
    {
        const char* gq = (const char*)(g_q + (size_t)(bt * 128) * KN);
        const char* gw = (const char*)(g_W + (size_t)(jt * 128) * KN);
#pragma unroll
        for (int i = 0; i < 4; i++) {
            int idx = tid + i * 256;            // 0..1023
            int row = idx >> 3;                 // 0..127
            int seg = (idx & 7) * 16;           // byte within 128B row
            swoff[i] = (uint32_t)(row * 128) + ((uint32_t)seg ^ (uint32_t)((row & 7) << 4));
            size_t gb = (size_t)row * (KN * 2) + seg;   // row stride 8192 B
            srcq[i] = gq + gb;
            srcw[i] = gw + gb;
        }
    }

    // ---- prefetch chunks 0..2 ----
#pragma unroll
    for (int s = 0; s < NSTG - 1; s++) {
        uint32_t base = sbase + s * STAGE;
        size_t koff = (size_t)s * 128;          // 64 fp16 = 128 bytes
#pragma unroll
        for (int i = 0; i < 4; i++) {
            cp16(base +         swoff[i], srcq[i] + koff);
            cp16(base + 16384 + swoff[i], srcw[i] + koff);
        }
        CP_COMMIT();
    }

    // ---- ldmatrix lane addressing ----
    const int a_row = warp_m * 32 + (lane & 15);           // + mt*16
    const uint32_t a_hi  = (uint32_t)((lane >> 4) * 16);
    const uint32_t a_swz = (uint32_t)((a_row & 7) << 4);   // invariant under +16
    const int b_g = lane >> 3;                              // 0..3
    const int b_row0 = warp_n * 64 + ((b_g >> 1) << 3) + (lane & 7);  // + i*16
    const uint32_t b_hi  = (uint32_t)((b_g & 1) * 16);
    const uint32_t b_swz = (uint32_t)((b_row0 & 7) << 4);  // invariant under +16

    float acc[2][8][4];
#pragma unroll
    for (int mt = 0; mt < 2; mt++)
#pragma unroll
        for (int nt = 0; nt < 8; nt++)
#pragma unroll
            for (int v = 0; v < 4; v++) acc[mt][nt][v] = 0.f;

    for (int c = 0; c < NCHUNK; c++) {
        CP_WAIT(2);              // chunk c landed (chunks c+1, c+2 may remain)
        __syncthreads();         // all threads see chunk c AND finished compute(c-1)

        // issue chunk c+3 into buffer (c+3)%4 == (c-1)%4, freed by the barrier above
        if (c + 3 < NCHUNK) {
            uint32_t base = sbase + ((c + 3) % NSTG) * STAGE;
            size_t koff = (size_t)(c + 3) * 128;
#pragma unroll
            for (int i = 0; i < 4; i++) {
                cp16(base +         swoff[i], srcq[i] + koff);
                cp16(base + 16384 + swoff[i], srcw[i] + koff);
            }
        }
        CP_COMMIT();             // fixed group accounting (empty at tail)

        const uint32_t bb = sbase + (c % NSTG) * STAGE;
#pragma unroll
        for (int ks = 0; ks < 4; ks++) {
            uint32_t a[2][4];
#pragma unroll
            for (int mt = 0; mt < 2; mt++)
                ldsm4(a[mt], bb + (uint32_t)((a_row + mt * 16) * 128)
                              + (((uint32_t)(ks * 32) + a_hi) ^ a_swz));
            uint32_t bw[8][2];
#pragma unroll
            for (int i = 0; i < 4; i++) {
                uint32_t ro = (uint32_t)((b_row0 + i * 16) * 128)
                            + (((uint32_t)(ks * 32) + b_hi) ^ b_swz);
                uint32_t r[4];
                ldsm4(r, bb + 16384 + ro);
                bw[2*i][0] = r[0]; bw[2*i][1] = r[1]; bw[2*i+1][0] = r[2]; bw[2*i+1][1] = r[3];
            }
#pragma unroll
            for (int mt = 0; mt < 2; mt++)
#pragma unroll
                for (int nt = 0; nt < 8; nt++)
                    mma16816_f16(acc[mt][nt], a[mt], bw[nt]);
        }
    }

    // ---- epilogue: out = acc*act + bias ----
    const float act = g_scale;
    const int orow0 = bt * 128 + warp_m * 32 + (lane >> 2);
    const int ocol0 = jt * 128 + warp_n * 64 + (lane & 3) * 2;
#pragma unroll
    for (int mt = 0; mt < 2; mt++) {
        const int r0 = orow0 + mt * 16;
#pragma unroll
        for (int nt = 0; nt < 8; nt++) {
            const int col = ocol0 + nt * 8;
            const float2 b2 = *(const float2*)(bias + col);
            float2 v0, v1;
            v0.x = acc[mt][nt][0] * act + b2.x;
            v0.y = acc[mt][nt][1] * act + b2.y;
            v1.x = acc[mt][nt][2] * act + b2.x;
            v1.y = acc[mt][nt][3] * act + b2.y;
            *(float2*)(out + (size_t)r0 * JM + col)       = v0;
            *(float2*)(out + (size_t)(r0 + 8) * JM + col) = v1;
        }
    }
}

// ---------------- launcher ----------------
extern "C" void kernel_launch(void* const* d_in, const int* in_sizes, int n_in,
                              void* d_out, int out_size) {
    const float *x = nullptr, *Ys = nullptr, *Zs = nullptr;
    const float *Ysc = nullptr, *Zsc = nullptr, *A = nullptr, *bias = nullptr;
    for (int i = 0; i < n_in; i++) {
        const int s = in_sizes[i];
        const float* p = (const float*)d_in[i];
        if (s == BATCH * KN && !x) x = p;                                        // 2097152
        else if (s == PP * JJ * KK * MM * LL) { if (!Ys) Ys = p; else Zs = p; }  // 4194304 x2
        else if (s == PP * JJ * KK) { if (!Ysc) Ysc = p; else Zsc = p; }         // 2048 x2
        else if (s == PP * JJ * KK * 4) A = p;                                   // 8192
        else if (s == JM) bias = p;                                              // 4096
    }
    float* out = (float*)d_out;

    k_minmax<<<256, 256>>>(x, (BATCH * KN) / 4);
    k_quant<<<(BATCH * KN) / 4 / 256, 256>>>(x);

    cudaFuncSetAttribute(k_buildw, cudaFuncAttributeMaxDynamicSharedMemorySize, BW_SMEM);
    k_buildw<<<JJ * KK, 256, BW_SMEM>>>(Ys, Zs, Ysc, Zsc, A);

    const int smem_bytes = NSTG * STAGE;   // 131072
    cudaFuncSetAttribute(k_gemm, cudaFuncAttributeMaxDynamicSharedMemorySize, smem_bytes);
    dim3 grid(JM / 128, BATCH / 128);
    k_gemm<<<grid, 256, smem_bytes>>>(bias, out);
}